// round 13
// baseline (speedup 1.0000x reference)
#include <cuda_runtime.h>
#include <cuda_fp16.h>
#include <math.h>
#include <stdint.h>

#define B_  16
#define LC  2048
#define LQ  1024
#define D_  512

// ---------------- scratch (device globals; cudaMalloc forbidden) ----------
__device__ float  g_S  [(size_t)B_ * LC * LQ];             // 134 MB: S[b,i,j]
__device__ __align__(16) __half g_At [(size_t)B_ * LQ * LC];  // A^T[b,j,i]
__device__ __align__(16) __half g_c16[(size_t)B_ * LC * D_];  // half(ctx) [b,i,d]
__device__ __align__(16) __half g_cT [(size_t)B_ * D_ * LC];  // half(ctx)^T [b,d,i]
__device__ __align__(16) __half g_qm [(size_t)LQ * D_];       // half(q*wm) [j,k]
__device__ float g_cb [B_ * LC];               // context @ wc
__device__ float g_m  [B_ * LQ];               // softmax max over i per (b,j)
__device__ float g_w2 [B_ * LQ];               // qmask[j] / Z[b,j]
__device__ float g_qmask[LQ];
__device__ float g_mp [16][B_ * LQ];           // per-128-i-strip partial max
__device__ float g_zp [16][B_ * LQ];           // per-128-i-strip partial Z

// ---------------- helpers ---------------------------------------------------
__device__ __forceinline__ uint32_t smem_u32(const void* p) {
    uint32_t a;
    asm("{ .reg .u64 t; cvta.to.shared.u64 t, %1; cvt.u32.u64 %0, t; }" : "=r"(a) : "l"(p));
    return a;
}
#define CP16(sm, gp) \
    asm volatile("cp.async.cg.shared.global [%0], [%1], 16;" :: "r"(sm), "l"(gp))
#define CP_COMMIT() asm volatile("cp.async.commit_group;" ::: "memory")

#define LDSM4(r0, r1, r2, r3, addr) \
    asm volatile("ldmatrix.sync.aligned.m8n8.x4.shared.b16 {%0,%1,%2,%3}, [%4];" \
        : "=r"(r0), "=r"(r1), "=r"(r2), "=r"(r3) : "r"(addr))

#define MMAH(c, a, b) \
    asm volatile("mma.sync.aligned.m16n8k16.row.col.f32.f16.f16.f32 " \
        "{%0,%1,%2,%3},{%4,%5,%6,%7},{%8,%9},{%0,%1,%2,%3};" \
        : "+f"((c)[0]), "+f"((c)[1]), "+f"((c)[2]), "+f"((c)[3]) \
        : "r"((a)[0]), "r"((a)[1]), "r"((a)[2]), "r"((a)[3]), \
          "r"((b)[0]), "r"((b)[1]))

// ---------------- kernel: cb = C@wc per row, qmask per query row ----------
__global__ void k_bias(const float* __restrict__ ctx,
                       const float* __restrict__ q,
                       const float* __restrict__ w) {
    int gwarp = (blockIdx.x * blockDim.x + threadIdx.x) >> 5;
    int lane  = threadIdx.x & 31;
    const int nrows = B_ * LC + LQ;
    if (gwarp >= nrows) return;
    if (gwarp < B_ * LC) {
        const float4* row = (const float4*)(ctx + (size_t)gwarp * D_);
        const float4* wc4 = (const float4*)w;
        float s = 0.f;
        #pragma unroll 4
        for (int k = lane; k < D_ / 4; k += 32) {
            float4 a = row[k], b = wc4[k];
            s += a.x * b.x + a.y * b.y + a.z * b.z + a.w * b.w;
        }
        #pragma unroll
        for (int o = 16; o; o >>= 1) s += __shfl_xor_sync(~0u, s, o);
        if (!lane) g_cb[gwarp] = s;
    } else {
        int j = gwarp - B_ * LC;
        const float4* row = (const float4*)(q + (size_t)j * D_);
        float s = 0.f;
        #pragma unroll 4
        for (int k = lane; k < D_ / 4; k += 32) {
            float4 a = row[k];
            s += a.x + a.y + a.z + a.w;
        }
        #pragma unroll
        for (int o = 16; o; o >>= 1) s += __shfl_xor_sync(~0u, s, o);
        if (!lane) g_qmask[j] = (s != 0.0f) ? 1.0f : 0.0f;
    }
}

// ---------------- kernel: ctx -> half c16 [i][d] + half cT [d][i] ----------
__global__ void k_prep(const float* __restrict__ ctx) {
    __shared__ float t[32][33];
    int b = blockIdx.z, i0 = blockIdx.y << 5, d0 = blockIdx.x << 5;
    int tx = threadIdx.x, ty = threadIdx.y;
    #pragma unroll
    for (int q = 0; q < 4; q++) {
        int r = ty + q * 8;
        float v = ctx[((size_t)b * LC + i0 + r) * D_ + d0 + tx];
        g_c16[((size_t)b * LC + i0 + r) * D_ + d0 + tx] = __float2half_rn(v);
        t[r][tx] = v;
    }
    __syncthreads();
    #pragma unroll
    for (int q = 0; q < 4; q++) {
        int r = ty + q * 8;
        g_cT[((size_t)b * D_ + d0 + r) * LC + i0 + tx] = __float2half_rn(t[tx][r]);
    }
}

// ---------------- kernel: qm[j,k] = half(q[j,k] * wm[k]) --------------------
__global__ void k_qm(const float* __restrict__ q, const float* __restrict__ w) {
    int j = blockIdx.x, t = threadIdx.x;
    const float4* q4 = (const float4*)(q + (size_t)j * D_);
    const float4* w4 = (const float4*)(w + 2 * D_);
    float4 a = q4[t], b = w4[t];
    __half2 h0 = __floats2half2_rn(a.x * b.x, a.y * b.y);
    __half2 h1 = __floats2half2_rn(a.z * b.z, a.w * b.w);
    __half* o = g_qm + (size_t)j * D_ + 4 * t;
    *(__half2*)(o)     = h0;
    *(__half2*)(o + 2) = h1;
}

// ---------------- unified K-major fp16 GEMM ---------------------------------
// Block 128(m) x 128(n), 128 threads, 4 warps of 64x64, BK=64 halves,
// 3-stage cp.async, loads pipelined into k-steps, A-fragments
// double-buffered across k-steps, 2 CTAs/SM.
// MODE 0: m=i (128 of LC), n=j, K=D_  : S = c16 · qm^T + cb  (+ stats partials)
// MODE 1: m=j (128 of LQ), n=d, K=LC : H = At · cT^T
#define STRD 72                    // halves per smem row (144 B, swizzle-free)
#define ASZH (128 * STRD)          // halves per operand per stage
#define STGH (2 * ASZH)            // halves per stage
#define GEMM_SMEM (3 * STGH * 2)   // 110592 B

template<int MODE>
__global__ __launch_bounds__(128, 2) void k_mma(float* __restrict__ gOut) {
    constexpr int KTOT = MODE ? LC : D_;
    constexpr int NKC  = KTOT / 64;

    extern __shared__ __half sh[];
    const int tid = threadIdx.x;
    const int b   = blockIdx.z;
    const int x0  = blockIdx.x * 128;
    const int y0  = blockIdx.y * 128;

    const __half* Abase = MODE ? g_At + ((size_t)b * LQ + y0) * LC
                               : g_c16 + ((size_t)b * LC + y0) * D_;
    const __half* Bbase = MODE ? g_cT + ((size_t)b * D_ + x0) * LC
                               : g_qm + (size_t)x0 * D_;

    const int lrow0 = tid >> 3;
    const int lseg  = (tid & 7) * 8;

    auto load_full = [&](int c, int st) {
        __half* dA = sh + st * STGH;
        __half* dB = dA + ASZH;
        const int k0 = c * 64;
        #pragma unroll
        for (int p = 0; p < 8; p++) {
            int row = lrow0 + p * 16;
            CP16(smem_u32(dA + row * STRD + lseg),
                 Abase + (size_t)row * KTOT + k0 + lseg);
        }
        #pragma unroll
        for (int p = 0; p < 8; p++) {
            int row = lrow0 + p * 16;
            CP16(smem_u32(dB + row * STRD + lseg),
                 Bbase + (size_t)row * KTOT + k0 + lseg);
        }
    };

    const int lane  = tid & 31, wrp = tid >> 5;
    const int mbase = (wrp & 1) * 64;
    const int nbase = (wrp >> 1) * 64;
    const int lr    = lane >> 2, lk = lane & 3;

    const uint32_t aoff = ((mbase + ((lane >> 3) & 1) * 8 + (lane & 7)) * STRD
                           + ((lane >> 4) & 1) * 8) * 2;
    const uint32_t boff = ((nbase + ((lane >> 4) & 1) * 8 + (lane & 7)) * STRD
                           + ((lane >> 3) & 1) * 8) * 2;

    float acc[4][8][4];
    #pragma unroll
    for (int mt = 0; mt < 4; mt++)
        #pragma unroll
        for (int nt = 0; nt < 8; nt++)
            #pragma unroll
            for (int e = 0; e < 4; e++) acc[mt][nt][e] = 0.f;

    // compute chunk from stage st; optionally interleave CP16s for chunk
    // cload into stage stl.  A-fragments double-buffered across k-steps.
    auto compute_load = [&](int st, bool doload, int cload, int stl) {
        const uint32_t aB = smem_u32(sh + st * STGH) + aoff;
        const uint32_t bB = smem_u32(sh + st * STGH + ASZH) + boff;
        __half* dA = sh + stl * STGH;
        __half* dB = dA + ASZH;
        const int k0 = cload * 64;
        uint32_t af[2][4][4], bf[8][2];
        // preload A fragments for kk=0
        #pragma unroll
        for (int mt = 0; mt < 4; mt++)
            LDSM4(af[0][mt][0], af[0][mt][1], af[0][mt][2], af[0][mt][3],
                  aB + (mt * 16 * STRD) * 2);
        #pragma unroll
        for (int kk = 0; kk < 4; kk++) {
            const int cur = kk & 1, nxt = cur ^ 1;
            // B fragments for this k-step
            #pragma unroll
            for (int p = 0; p < 4; p++)
                LDSM4(bf[2 * p][0], bf[2 * p][1], bf[2 * p + 1][0], bf[2 * p + 1][1],
                      bB + (p * 16 * STRD + kk * 16) * 2);
            // A prefetch for next k-step
            if (kk < 3) {
                #pragma unroll
                for (int mt = 0; mt < 4; mt++)
                    LDSM4(af[nxt][mt][0], af[nxt][mt][1], af[nxt][mt][2], af[nxt][mt][3],
                          aB + (mt * 16 * STRD + (kk + 1) * 16) * 2);
            }
            if (doload) {
                #pragma unroll
                for (int u = 0; u < 2; u++) {
                    int row = lrow0 + (kk * 2 + u) * 16;
                    CP16(smem_u32(dA + row * STRD + lseg),
                         Abase + (size_t)row * KTOT + k0 + lseg);
                    CP16(smem_u32(dB + row * STRD + lseg),
                         Bbase + (size_t)row * KTOT + k0 + lseg);
                }
            }
            #pragma unroll
            for (int mt = 0; mt < 4; mt++)
                #pragma unroll
                for (int nt = 0; nt < 8; nt++)
                    MMAH(acc[mt][nt], af[cur][mt], bf[nt]);
        }
    };

    load_full(0, 0); CP_COMMIT();
    load_full(1, 1); CP_COMMIT();
    int st_c = 0, st_l = 2;
    for (int c = 0; c < NKC; c++) {
        asm volatile("cp.async.wait_group 1;" ::: "memory");
        __syncthreads();
        compute_load(st_c, c + 2 < NKC, c + 2, st_l);
        CP_COMMIT();
        st_c = (st_c == 2) ? 0 : st_c + 1;
        st_l = (st_l == 2) ? 0 : st_l + 1;
    }

    if (MODE == 0) {
        #pragma unroll
        for (int mt = 0; mt < 4; mt++) {
            int i = y0 + mbase + mt * 16 + lr;
            float c0 = g_cb[b * LC + i];
            float c8 = g_cb[b * LC + i + 8];
            #pragma unroll
            for (int nt = 0; nt < 8; nt++) {
                acc[mt][nt][0] += c0; acc[mt][nt][1] += c0;
                acc[mt][nt][2] += c8; acc[mt][nt][3] += c8;
                int j = x0 + nbase + nt * 8 + 2 * lk;
                *(float2*)(g_S + ((size_t)(b * LC + i)) * LQ + j) =
                    make_float2(acc[mt][nt][0], acc[mt][nt][1]);
                *(float2*)(g_S + ((size_t)(b * LC + i + 8)) * LQ + j) =
                    make_float2(acc[mt][nt][2], acc[mt][nt][3]);
            }
        }
        float pm[16], pz[16];
        #pragma unroll
        for (int nt = 0; nt < 8; nt++) {
            float m0 = -1e30f, m1 = -1e30f;
            #pragma unroll
            for (int mt = 0; mt < 4; mt++) {
                m0 = fmaxf(m0, fmaxf(acc[mt][nt][0], acc[mt][nt][2]));
                m1 = fmaxf(m1, fmaxf(acc[mt][nt][1], acc[mt][nt][3]));
            }
            float z0 = 0.f, z1 = 0.f;
            #pragma unroll
            for (int mt = 0; mt < 4; mt++) {
                z0 += __expf(acc[mt][nt][0] - m0) + __expf(acc[mt][nt][2] - m0);
                z1 += __expf(acc[mt][nt][1] - m1) + __expf(acc[mt][nt][3] - m1);
            }
            pm[2 * nt] = m0; pz[2 * nt] = z0;
            pm[2 * nt + 1] = m1; pz[2 * nt + 1] = z1;
        }
        #pragma unroll
        for (int off = 4; off <= 16; off <<= 1) {
            #pragma unroll
            for (int c2 = 0; c2 < 16; c2++) {
                float mo = __shfl_xor_sync(~0u, pm[c2], off);
                float zo = __shfl_xor_sync(~0u, pz[c2], off);
                float mn = fmaxf(pm[c2], mo);
                pz[c2] = pz[c2] * __expf(pm[c2] - mn) + zo * __expf(mo - mn);
                pm[c2] = mn;
            }
        }
        float* red = (float*)sh;
        __syncthreads();
        if (lane < 4) {
            #pragma unroll
            for (int c2 = 0; c2 < 16; c2++) {
                int j = nbase + (c2 >> 1) * 8 + 2 * lane + (c2 & 1);
                red[(wrp & 1) * 256 + j]       = pm[c2];
                red[(wrp & 1) * 256 + 128 + j] = pz[c2];
            }
        }
        __syncthreads();
        if (tid < 128) {
            float ma = red[tid],       mb2 = red[256 + tid];
            float za = red[128 + tid], zb  = red[384 + tid];
            float M = fmaxf(ma, mb2);
            float Z = za * __expf(ma - M) + zb * __expf(mb2 - M);
            g_mp[blockIdx.y][b * LQ + x0 + tid] = M;
            g_zp[blockIdx.y][b * LQ + x0 + tid] = Z;
        }
    } else {
        #pragma unroll
        for (int mt = 0; mt < 4; mt++) {
            int j = y0 + mbase + mt * 16 + lr;
            #pragma unroll
            for (int nt = 0; nt < 8; nt++) {
                int d = x0 + nbase + nt * 8 + 2 * lk;
                float2 v0 = make_float2(acc[mt][nt][0], acc[mt][nt][1]);
                float2 v1 = make_float2(acc[mt][nt][2], acc[mt][nt][3]);
                *(float2*)(gOut + ((size_t)(b * LQ + j)) * D_ + d)     = v0;
                *(float2*)(gOut + ((size_t)(b * LQ + j + 8)) * D_ + d) = v1;
            }
        }
    }
}

// ---------------- kernel: combine 16 strips ---------------------------------
__global__ void k_stats2() {
    int idx = blockIdx.x * blockDim.x + threadIdx.x;
    float M = g_mp[0][idx];
    #pragma unroll
    for (int s = 1; s < 16; s++) M = fmaxf(M, g_mp[s][idx]);
    float Z = 0.f;
    #pragma unroll
    for (int s = 0; s < 16; s++) Z += g_zp[s][idx] * __expf(g_mp[s][idx] - M);
    g_m [idx] = M;
    g_w2[idx] = g_qmask[idx & (LQ - 1)] / Z;
}

// ---------------- kernel: A^T (half) + colsum + G (fused) -------------------
__global__ __launch_bounds__(256) void k_ATG(const float* __restrict__ ctx,
                                             float* __restrict__ G) {
    const int b  = blockIdx.y;
    const int i0 = blockIdx.x << 5;
    const int t  = threadIdx.x;
    __shared__ float sm[LQ], sw[LQ];
    __shared__ float As[32][33];
    __shared__ float scs[32];
    for (int k = t; k < LQ; k += 256) {
        sm[k] = g_m [b * LQ + k];
        sw[k] = g_w2[b * LQ + k];
    }
    __syncthreads();

    const int ii = t >> 3;
    const int jq = (t & 7) * 4;
    float cs = 0.f;

    for (int jt = 0; jt < 32; jt++) {
        int j = jt * 32 + jq;
        float4 s = *(const float4*)(g_S + ((size_t)(b * LC + i0 + ii)) * LQ + j);
        float a0 = __expf(s.x - sm[j + 0]) * sw[j + 0];
        float a1 = __expf(s.y - sm[j + 1]) * sw[j + 1];
        float a2 = __expf(s.z - sm[j + 2]) * sw[j + 2];
        float a3 = __expf(s.w - sm[j + 3]) * sw[j + 3];
        cs += (a0 + a1) + (a2 + a3);
        As[ii][jq + 0] = a0;
        As[ii][jq + 1] = a1;
        As[ii][jq + 2] = a2;
        As[ii][jq + 3] = a3;
        __syncthreads();
        int jj = t >> 3;
        int iq = (t & 7) * 4;
        __half2 p0 = __floats2half2_rn(As[iq + 0][jj], As[iq + 1][jj]);
        __half2 p1 = __floats2half2_rn(As[iq + 2][jj], As[iq + 3][jj]);
        __half* Arow = g_At + ((size_t)(b * LQ + jt * 32 + jj)) * LC + i0 + iq;
        *(__half2*)(Arow)     = p0;
        *(__half2*)(Arow + 2) = p1;
        __syncthreads();
    }
    cs += __shfl_xor_sync(~0u, cs, 4);
    cs += __shfl_xor_sync(~0u, cs, 2);
    cs += __shfl_xor_sync(~0u, cs, 1);
    if ((t & 7) == 0) scs[ii] = cs;
    __syncthreads();
    for (int idx = t; idx < 32 * 128; idx += 256) {
        int row = idx >> 7, c = idx & 127;
        float4 v = ((const float4*)(ctx + ((size_t)(b * LC + i0 + row)) * D_))[c];
        float s = scs[row];
        float4* g4 = (float4*)(G + ((size_t)(b * LC + i0 + row)) * 2 * D_);
        g4[c] = v;
        g4[128 + c] = make_float4(v.x * s, v.y * s, v.z * s, v.w * s);
    }
}

// ---------------- launch -----------------------------------------------------
extern "C" void kernel_launch(void* const* d_in, const int* in_sizes, int n_in,
                              void* d_out, int out_size) {
    const float *ctx = nullptr, *q = nullptr, *w = nullptr;
    for (int i = 0; i < n_in; i++) {
        if      (in_sizes[i] == B_ * LC * D_) ctx = (const float*)d_in[i];
        else if (in_sizes[i] == LQ * D_)      q   = (const float*)d_in[i];
        else if (in_sizes[i] == 3 * D_)       w   = (const float*)d_in[i];
    }
    float* G = (float*)d_out;                              // (B, LC, 2D)
    float* H = (float*)d_out + (size_t)B_ * LC * 2 * D_;   // (B, LQ, D)

    cudaFuncSetAttribute(k_mma<0>, cudaFuncAttributeMaxDynamicSharedMemorySize, GEMM_SMEM);
    cudaFuncSetAttribute(k_mma<1>, cudaFuncAttributeMaxDynamicSharedMemorySize, GEMM_SMEM);

    k_bias   <<<(B_ * LC + LQ + 7) / 8, 256>>>(ctx, q, w);
    k_prep   <<<dim3(D_ / 32, LC / 32, B_), dim3(32, 8)>>>(ctx);
    k_qm     <<<LQ, 128>>>(q, w);
    k_mma<0> <<<dim3(LQ / 128, LC / 128, B_), 128, GEMM_SMEM>>>(nullptr);
    k_stats2 <<<B_ * LQ / 256, 256>>>();
    k_ATG    <<<dim3(LC / 32, B_), 256>>>(ctx, G);
    k_mma<1> <<<dim3(D_ / 128, LQ / 128, B_), 128, GEMM_SMEM>>>(H);
}

// round 14
// speedup vs baseline: 1.0258x; 1.0258x over previous
#include <cuda_runtime.h>
#include <cuda_fp16.h>
#include <math.h>
#include <stdint.h>

#define B_  16
#define LC  2048
#define LQ  1024
#define D_  512

// ---------------- scratch (device globals; cudaMalloc forbidden) ----------
__device__ float  g_S  [(size_t)B_ * LC * LQ];             // S[b,i,j]
__device__ __align__(16) __half g_At [(size_t)B_ * LQ * LC];  // A^T[b,j,i]
__device__ __align__(16) __half g_c16[(size_t)B_ * LC * D_];  // half(ctx) [b,i,d]
__device__ __align__(16) __half g_cT [(size_t)B_ * D_ * LC];  // half(ctx)^T [b,d,i]
__device__ __align__(16) __half g_qm [(size_t)LQ * D_];       // half(q*wm) [j,k]
__device__ float g_cb [B_ * LC];               // context @ wc
__device__ float g_cbp[16][B_ * LC];           // per-d-tile partial dots
__device__ float g_m  [B_ * LQ];               // softmax max over i per (b,j)
__device__ float g_w2 [B_ * LQ];               // qmask[j] / Z[b,j]
__device__ float g_qmask[LQ];
__device__ float g_mp [16][B_ * LQ];           // per-128-i-strip partial max
__device__ float g_zp [16][B_ * LQ];           // per-128-i-strip partial Z

// ---------------- helpers ---------------------------------------------------
__device__ __forceinline__ uint32_t smem_u32(const void* p) {
    uint32_t a;
    asm("{ .reg .u64 t; cvta.to.shared.u64 t, %1; cvt.u32.u64 %0, t; }" : "=r"(a) : "l"(p));
    return a;
}
#define CP16(sm, gp) \
    asm volatile("cp.async.cg.shared.global [%0], [%1], 16;" :: "r"(sm), "l"(gp))
#define CP_COMMIT() asm volatile("cp.async.commit_group;" ::: "memory")

#define LDSM4(r0, r1, r2, r3, addr) \
    asm volatile("ldmatrix.sync.aligned.m8n8.x4.shared.b16 {%0,%1,%2,%3}, [%4];" \
        : "=r"(r0), "=r"(r1), "=r"(r2), "=r"(r3) : "r"(addr))

#define MMAH(c, a, b) \
    asm volatile("mma.sync.aligned.m16n8k16.row.col.f32.f16.f16.f32 " \
        "{%0,%1,%2,%3},{%4,%5,%6,%7},{%8,%9},{%0,%1,%2,%3};" \
        : "+f"((c)[0]), "+f"((c)[1]), "+f"((c)[2]), "+f"((c)[3]) \
        : "r"((a)[0]), "r"((a)[1]), "r"((a)[2]), "r"((a)[3]), \
          "r"((b)[0]), "r"((b)[1]))

// ---------------- kernel: prep ctx (half + half^T) + cb partials ------------
// grid (16, 64, 16), block (32, 8).  cb partial computed from the fp32
// staging tile AFTER the barrier: 4 FMA + 3 shfl per thread.
__global__ void k_prep(const float* __restrict__ ctx, const float* __restrict__ w) {
    __shared__ float t[32][33];
    int b = blockIdx.z, i0 = blockIdx.y << 5, d0 = blockIdx.x << 5;
    int tx = threadIdx.x, ty = threadIdx.y;
    #pragma unroll
    for (int q = 0; q < 4; q++) {
        int r = ty + q * 8;
        float v = ctx[((size_t)b * LC + i0 + r) * D_ + d0 + tx];
        g_c16[((size_t)b * LC + i0 + r) * D_ + d0 + tx] = __float2half_rn(v);
        t[r][tx] = v;
    }
    __syncthreads();
    #pragma unroll
    for (int q = 0; q < 4; q++) {
        int r = ty + q * 8;
        g_cT[((size_t)b * D_ + d0 + r) * LC + i0 + tx] = __float2half_rn(t[tx][r]);
    }
    // cb partial: warp ty handles rows 4*ty..4*ty+3; 8 lanes per row
    int r  = 4 * ty + (tx >> 3);
    int k4 = (tx & 7) * 4;
    const float* wc = w + d0 + k4;
    float s = t[r][k4] * wc[0] + t[r][k4 + 1] * wc[1]
            + t[r][k4 + 2] * wc[2] + t[r][k4 + 3] * wc[3];
    s += __shfl_xor_sync(~0u, s, 4);
    s += __shfl_xor_sync(~0u, s, 2);
    s += __shfl_xor_sync(~0u, s, 1);
    if ((tx & 7) == 0) g_cbp[blockIdx.x][b * LC + i0 + r] = s;
}

// ---------------- kernel: sum cb partials ------------------------------------
__global__ void k_cbsum() {
    int idx = blockIdx.x * blockDim.x + threadIdx.x;   // b*LC + i
    float s = 0.f;
    #pragma unroll
    for (int p = 0; p < 16; p++) s += g_cbp[p][idx];
    g_cb[idx] = s;
}

// ---------------- kernel: qm row (half) + qmask -------------------------------
__global__ void k_qm(const float* __restrict__ q, const float* __restrict__ w) {
    int j = blockIdx.x, t = threadIdx.x;
    const float4* q4 = (const float4*)(q + (size_t)j * D_);
    const float4* w4 = (const float4*)(w + 2 * D_);
    float4 a = q4[t], b = w4[t];
    __half2 h0 = __floats2half2_rn(a.x * b.x, a.y * b.y);
    __half2 h1 = __floats2half2_rn(a.z * b.z, a.w * b.w);
    __half* o = g_qm + (size_t)j * D_ + 4 * t;
    *(__half2*)(o)     = h0;
    *(__half2*)(o + 2) = h1;
    float s = (a.x + a.y) + (a.z + a.w);
    #pragma unroll
    for (int of = 16; of; of >>= 1) s += __shfl_xor_sync(~0u, s, of);
    __shared__ float sr[4];
    if (!(t & 31)) sr[t >> 5] = s;
    __syncthreads();
    if (!t) g_qmask[j] = ((sr[0] + sr[1] + sr[2] + sr[3]) != 0.0f) ? 1.0f : 0.0f;
}

// ---------------- unified K-major fp16 GEMM (round-12 structure) ------------
#define STRD 72                    // halves per smem row (144 B, swizzle-free)
#define ASZH (128 * STRD)
#define STGH (2 * ASZH)
#define GEMM_SMEM (3 * STGH * 2)   // 110592 B

template<int MODE>
__global__ __launch_bounds__(128, 2) void k_mma(float* __restrict__ gOut) {
    constexpr int KTOT = MODE ? LC : D_;
    constexpr int NKC  = KTOT / 64;

    extern __shared__ __half sh[];
    const int tid = threadIdx.x;
    const int b   = blockIdx.z;
    const int x0  = blockIdx.x * 128;
    const int y0  = blockIdx.y * 128;

    const __half* Abase = MODE ? g_At + ((size_t)b * LQ + y0) * LC
                               : g_c16 + ((size_t)b * LC + y0) * D_;
    const __half* Bbase = MODE ? g_cT + ((size_t)b * D_ + x0) * LC
                               : g_qm + (size_t)x0 * D_;

    const int lrow0 = tid >> 3;
    const int lseg  = (tid & 7) * 8;

    auto load_full = [&](int c, int st) {
        __half* dA = sh + st * STGH;
        __half* dB = dA + ASZH;
        const int k0 = c * 64;
        #pragma unroll
        for (int p = 0; p < 8; p++) {
            int row = lrow0 + p * 16;
            CP16(smem_u32(dA + row * STRD + lseg),
                 Abase + (size_t)row * KTOT + k0 + lseg);
        }
        #pragma unroll
        for (int p = 0; p < 8; p++) {
            int row = lrow0 + p * 16;
            CP16(smem_u32(dB + row * STRD + lseg),
                 Bbase + (size_t)row * KTOT + k0 + lseg);
        }
    };

    const int lane  = tid & 31, wrp = tid >> 5;
    const int mbase = (wrp & 1) * 64;
    const int nbase = (wrp >> 1) * 64;
    const int lr    = lane >> 2, lk = lane & 3;

    const uint32_t aoff = ((mbase + ((lane >> 3) & 1) * 8 + (lane & 7)) * STRD
                           + ((lane >> 4) & 1) * 8) * 2;
    const uint32_t boff = ((nbase + ((lane >> 4) & 1) * 8 + (lane & 7)) * STRD
                           + ((lane >> 3) & 1) * 8) * 2;

    float acc[4][8][4];
    #pragma unroll
    for (int mt = 0; mt < 4; mt++)
        #pragma unroll
        for (int nt = 0; nt < 8; nt++)
            #pragma unroll
            for (int e = 0; e < 4; e++) acc[mt][nt][e] = 0.f;

    auto compute_load = [&](int st, bool doload, int cload, int stl) {
        const uint32_t aB = smem_u32(sh + st * STGH) + aoff;
        const uint32_t bB = smem_u32(sh + st * STGH + ASZH) + boff;
        __half* dA = sh + stl * STGH;
        __half* dB = dA + ASZH;
        const int k0 = cload * 64;
        #pragma unroll
        for (int kk = 0; kk < 4; kk++) {
            uint32_t af[4][4], bf[8][2];
            #pragma unroll
            for (int mt = 0; mt < 4; mt++)
                LDSM4(af[mt][0], af[mt][1], af[mt][2], af[mt][3],
                      aB + (mt * 16 * STRD + kk * 16) * 2);
            #pragma unroll
            for (int p = 0; p < 4; p++)
                LDSM4(bf[2 * p][0], bf[2 * p][1], bf[2 * p + 1][0], bf[2 * p + 1][1],
                      bB + (p * 16 * STRD + kk * 16) * 2);
            if (doload) {
                #pragma unroll
                for (int u = 0; u < 2; u++) {
                    int row = lrow0 + (kk * 2 + u) * 16;
                    CP16(smem_u32(dA + row * STRD + lseg),
                         Abase + (size_t)row * KTOT + k0 + lseg);
                    CP16(smem_u32(dB + row * STRD + lseg),
                         Bbase + (size_t)row * KTOT + k0 + lseg);
                }
            }
            #pragma unroll
            for (int mt = 0; mt < 4; mt++)
                #pragma unroll
                for (int nt = 0; nt < 8; nt++)
                    MMAH(acc[mt][nt], af[mt], bf[nt]);
        }
    };

    load_full(0, 0); CP_COMMIT();
    load_full(1, 1); CP_COMMIT();
    int st_c = 0, st_l = 2;
    for (int c = 0; c < NKC; c++) {
        asm volatile("cp.async.wait_group 1;" ::: "memory");
        __syncthreads();
        compute_load(st_c, c + 2 < NKC, c + 2, st_l);
        CP_COMMIT();
        st_c = (st_c == 2) ? 0 : st_c + 1;
        st_l = (st_l == 2) ? 0 : st_l + 1;
    }

    if (MODE == 0) {
        #pragma unroll
        for (int mt = 0; mt < 4; mt++) {
            int i = y0 + mbase + mt * 16 + lr;
            float c0 = g_cb[b * LC + i];
            float c8 = g_cb[b * LC + i + 8];
            #pragma unroll
            for (int nt = 0; nt < 8; nt++) {
                acc[mt][nt][0] += c0; acc[mt][nt][1] += c0;
                acc[mt][nt][2] += c8; acc[mt][nt][3] += c8;
                int j = x0 + nbase + nt * 8 + 2 * lk;
                *(float2*)(g_S + ((size_t)(b * LC + i)) * LQ + j) =
                    make_float2(acc[mt][nt][0], acc[mt][nt][1]);
                *(float2*)(g_S + ((size_t)(b * LC + i + 8)) * LQ + j) =
                    make_float2(acc[mt][nt][2], acc[mt][nt][3]);
            }
        }
        float pm[16], pz[16];
        #pragma unroll
        for (int nt = 0; nt < 8; nt++) {
            float m0 = -1e30f, m1 = -1e30f;
            #pragma unroll
            for (int mt = 0; mt < 4; mt++) {
                m0 = fmaxf(m0, fmaxf(acc[mt][nt][0], acc[mt][nt][2]));
                m1 = fmaxf(m1, fmaxf(acc[mt][nt][1], acc[mt][nt][3]));
            }
            float z0 = 0.f, z1 = 0.f;
            #pragma unroll
            for (int mt = 0; mt < 4; mt++) {
                z0 += __expf(acc[mt][nt][0] - m0) + __expf(acc[mt][nt][2] - m0);
                z1 += __expf(acc[mt][nt][1] - m1) + __expf(acc[mt][nt][3] - m1);
            }
            pm[2 * nt] = m0; pz[2 * nt] = z0;
            pm[2 * nt + 1] = m1; pz[2 * nt + 1] = z1;
        }
        #pragma unroll
        for (int off = 4; off <= 16; off <<= 1) {
            #pragma unroll
            for (int c2 = 0; c2 < 16; c2++) {
                float mo = __shfl_xor_sync(~0u, pm[c2], off);
                float zo = __shfl_xor_sync(~0u, pz[c2], off);
                float mn = fmaxf(pm[c2], mo);
                pz[c2] = pz[c2] * __expf(pm[c2] - mn) + zo * __expf(mo - mn);
                pm[c2] = mn;
            }
        }
        float* red = (float*)sh;
        __syncthreads();
        if (lane < 4) {
            #pragma unroll
            for (int c2 = 0; c2 < 16; c2++) {
                int j = nbase + (c2 >> 1) * 8 + 2 * lane + (c2 & 1);
                red[(wrp & 1) * 256 + j]       = pm[c2];
                red[(wrp & 1) * 256 + 128 + j] = pz[c2];
            }
        }
        __syncthreads();
        if (tid < 128) {
            float ma = red[tid],       mb2 = red[256 + tid];
            float za = red[128 + tid], zb  = red[384 + tid];
            float M = fmaxf(ma, mb2);
            float Z = za * __expf(ma - M) + zb * __expf(mb2 - M);
            g_mp[blockIdx.y][b * LQ + x0 + tid] = M;
            g_zp[blockIdx.y][b * LQ + x0 + tid] = Z;
        }
    } else {
        #pragma unroll
        for (int mt = 0; mt < 4; mt++) {
            int j = y0 + mbase + mt * 16 + lr;
            #pragma unroll
            for (int nt = 0; nt < 8; nt++) {
                int d = x0 + nbase + nt * 8 + 2 * lk;
                float2 v0 = make_float2(acc[mt][nt][0], acc[mt][nt][1]);
                float2 v1 = make_float2(acc[mt][nt][2], acc[mt][nt][3]);
                *(float2*)(gOut + ((size_t)(b * LQ + j)) * D_ + d)     = v0;
                *(float2*)(gOut + ((size_t)(b * LQ + j + 8)) * D_ + d) = v1;
            }
        }
    }
}

// ---------------- kernel: combine 16 strips ---------------------------------
__global__ void k_stats2() {
    int idx = blockIdx.x * blockDim.x + threadIdx.x;
    float M = g_mp[0][idx];
    #pragma unroll
    for (int s = 1; s < 16; s++) M = fmaxf(M, g_mp[s][idx]);
    float Z = 0.f;
    #pragma unroll
    for (int s = 0; s < 16; s++) Z += g_zp[s][idx] * __expf(g_mp[s][idx] - M);
    g_m [idx] = M;
    g_w2[idx] = g_qmask[idx & (LQ - 1)] / Z;
}

// ---------------- kernel: A^T (half) + colsum + G (fused) -------------------
__global__ __launch_bounds__(256) void k_ATG(const float* __restrict__ ctx,
                                             float* __restrict__ G) {
    const int b  = blockIdx.y;
    const int i0 = blockIdx.x << 5;
    const int t  = threadIdx.x;
    __shared__ float sm[LQ], sw[LQ];
    __shared__ float As[32][33];
    __shared__ float scs[32];
    for (int k = t; k < LQ; k += 256) {
        sm[k] = g_m [b * LQ + k];
        sw[k] = g_w2[b * LQ + k];
    }
    __syncthreads();

    const int ii = t >> 3;
    const int jq = (t & 7) * 4;
    float cs = 0.f;

    for (int jt = 0; jt < 32; jt++) {
        int j = jt * 32 + jq;
        float4 s = *(const float4*)(g_S + ((size_t)(b * LC + i0 + ii)) * LQ + j);
        float a0 = __expf(s.x - sm[j + 0]) * sw[j + 0];
        float a1 = __expf(s.y - sm[j + 1]) * sw[j + 1];
        float a2 = __expf(s.z - sm[j + 2]) * sw[j + 2];
        float a3 = __expf(s.w - sm[j + 3]) * sw[j + 3];
        cs += (a0 + a1) + (a2 + a3);
        As[ii][jq + 0] = a0;
        As[ii][jq + 1] = a1;
        As[ii][jq + 2] = a2;
        As[ii][jq + 3] = a3;
        __syncthreads();
        int jj = t >> 3;
        int iq = (t & 7) * 4;
        __half2 p0 = __floats2half2_rn(As[iq + 0][jj], As[iq + 1][jj]);
        __half2 p1 = __floats2half2_rn(As[iq + 2][jj], As[iq + 3][jj]);
        __half* Arow = g_At + ((size_t)(b * LQ + jt * 32 + jj)) * LC + i0 + iq;
        *(__half2*)(Arow)     = p0;
        *(__half2*)(Arow + 2) = p1;
        __syncthreads();
    }
    cs += __shfl_xor_sync(~0u, cs, 4);
    cs += __shfl_xor_sync(~0u, cs, 2);
    cs += __shfl_xor_sync(~0u, cs, 1);
    if ((t & 7) == 0) scs[ii] = cs;
    __syncthreads();
    for (int idx = t; idx < 32 * 128; idx += 256) {
        int row = idx >> 7, c = idx & 127;
        float4 v = ((const float4*)(ctx + ((size_t)(b * LC + i0 + row)) * D_))[c];
        float s = scs[row];
        float4* g4 = (float4*)(G + ((size_t)(b * LC + i0 + row)) * 2 * D_);
        g4[c] = v;
        g4[128 + c] = make_float4(v.x * s, v.y * s, v.z * s, v.w * s);
    }
}

// ---------------- launch -----------------------------------------------------
extern "C" void kernel_launch(void* const* d_in, const int* in_sizes, int n_in,
                              void* d_out, int out_size) {
    const float *ctx = nullptr, *q = nullptr, *w = nullptr;
    for (int i = 0; i < n_in; i++) {
        if      (in_sizes[i] == B_ * LC * D_) ctx = (const float*)d_in[i];
        else if (in_sizes[i] == LQ * D_)      q   = (const float*)d_in[i];
        else if (in_sizes[i] == 3 * D_)       w   = (const float*)d_in[i];
    }
    float* G = (float*)d_out;                              // (B, LC, 2D)
    float* H = (float*)d_out + (size_t)B_ * LC * 2 * D_;   // (B, LQ, D)

    cudaFuncSetAttribute(k_mma<0>, cudaFuncAttributeMaxDynamicSharedMemorySize, GEMM_SMEM);
    cudaFuncSetAttribute(k_mma<1>, cudaFuncAttributeMaxDynamicSharedMemorySize, GEMM_SMEM);

    k_prep   <<<dim3(D_ / 32, LC / 32, B_), dim3(32, 8)>>>(ctx, w);
    k_cbsum  <<<B_ * LC / 256, 256>>>();
    k_qm     <<<LQ, 128>>>(q, w);
    k_mma<0> <<<dim3(LQ / 128, LC / 128, B_), 128, GEMM_SMEM>>>(nullptr);
    k_stats2 <<<B_ * LQ / 256, 256>>>();
    k_ATG    <<<dim3(LC / 32, B_), 256>>>(ctx, G);
    k_mma<1> <<<dim3(D_ / 128, LQ / 128, B_), 128, GEMM_SMEM>>>(H);
}